// round 4
// baseline (speedup 1.0000x reference)
#include <cuda_runtime.h>
#include <cstdint>

#define NN 100000
#define NE 1000000

typedef unsigned long long u64;

// ---------------- device scratch ----------------
__device__ float g_P0[(size_t)NN * 64];
__device__ float g_P1[(size_t)NN * 64];
__device__ float g_agg[(size_t)NN * 64];
__device__ float g_xs[3][(size_t)NN * 64];
__device__ int   g_is64;

// ---------------- f32x2 packed helpers (FFMA2: 2x fp32 rate on Blackwell) ---
__device__ __forceinline__ u64 pk2(float x, float y) {
    u64 r; asm("mov.b64 %0,{%1,%2};" : "=l"(r) : "f"(x), "f"(y)); return r;
}
__device__ __forceinline__ void up2(u64 v, float& x, float& y) {
    asm("mov.b64 {%0,%1},%2;" : "=f"(x), "=f"(y) : "l"(v));
}
__device__ __forceinline__ u64 ff2(u64 a, u64 b, u64 c) {
    u64 d; asm("fma.rn.f32x2 %0,%1,%2,%3;" : "=l"(d) : "l"(a), "l"(b), "l"(c));
    return d;
}

// ---------------- dtype detection (int64 vs int32 edge_index) ---------------
__global__ void detect_k(const int* __restrict__ ei) {
    if (threadIdx.x == 0 && blockIdx.x == 0) {
        int is64 = 1;
        for (int e = 0; e < 64; e++)
            if (ei[2 * e + 1] != 0) { is64 = 0; break; }
        g_is64 = is64;
    }
}

// ---------------- edge scatter-add: agg[dst] += w * P[src] ------------------
// 8 threads per edge, 8 channels each (2 x float4)
__global__ __launch_bounds__(256) void edge_k(const int* __restrict__ ei,
                                              const float* __restrict__ ew,
                                              const float* __restrict__ P,
                                              float* __restrict__ agg) {
    int t = blockIdx.x * 256 + threadIdx.x;
    int e = t >> 3;
    int g = (t & 7) * 8;
    int src, dst;
    if (g_is64) {
        const long long* e64 = (const long long*)ei;
        src = (int)e64[e];
        dst = (int)e64[NE + e];
    } else {
        src = ei[e];
        dst = ei[NE + e];
    }
    float w = ew[e];
    const float4* vp = (const float4*)(P + (size_t)src * 64 + g);
    float4 v0 = vp[0], v1 = vp[1];
    float* p = agg + (size_t)dst * 64 + g;
    asm volatile("red.global.add.v4.f32 [%0],{%1,%2,%3,%4};"
                 :: "l"(p), "f"(v0.x * w), "f"(v0.y * w), "f"(v0.z * w), "f"(v0.w * w)
                 : "memory");
    asm volatile("red.global.add.v4.f32 [%0],{%1,%2,%3,%4};"
                 :: "l"(p + 4), "f"(v1.x * w), "f"(v1.y * w), "f"(v1.z * w), "f"(v1.w * w)
                 : "memory");
}

// ---------------- input projection: P = x @ W1_0  (K=128), zero AGG --------
__global__ __launch_bounds__(256) void input_k(const float* __restrict__ X,
                                               const float* __restrict__ W,
                                               float* __restrict__ P,
                                               float* __restrict__ AGG) {
    extern __shared__ float sm[];
    float* As = sm;              // 64 x 132
    float* Bs = sm + 64 * 132;   // 128 x 64
    int tid = threadIdx.x, m0 = blockIdx.x * 64;

    for (int i = tid; i < 64 * 32; i += 256) {
        int r = i >> 5, c4 = i & 31, m = m0 + r;
        float4 v = make_float4(0.f, 0.f, 0.f, 0.f);
        if (m < NN) v = *(const float4*)(X + (size_t)m * 128 + c4 * 4);
        *(float4*)(As + r * 132 + c4 * 4) = v;
    }
    for (int i = tid; i < 128 * 16; i += 256)
        ((float4*)Bs)[i] = ((const float4*)W)[i];
    for (int i = tid; i < 64 * 16; i += 256) {
        int r = i >> 4, m = m0 + r;
        if (m < NN)
            *(float4*)(AGG + (size_t)m * 64 + (i & 15) * 4) = make_float4(0.f, 0.f, 0.f, 0.f);
    }
    __syncthreads();

    int tx = tid & 7, ty = tid >> 3, r0 = ty * 2;
    const u64* B8 = (const u64*)Bs;
    u64 acc[2][4] = {};
#pragma unroll 4
    for (int k = 0; k < 128; k++) {
        float a0 = As[r0 * 132 + k], a1 = As[r0 * 132 + 132 + k];
        u64 ap0 = pk2(a0, a0), ap1 = pk2(a1, a1);
        ulonglong2 b0 = *(const ulonglong2*)(B8 + k * 32 + tx * 4);
        ulonglong2 b1 = *(const ulonglong2*)(B8 + k * 32 + tx * 4 + 2);
        acc[0][0] = ff2(ap0, b0.x, acc[0][0]); acc[0][1] = ff2(ap0, b0.y, acc[0][1]);
        acc[0][2] = ff2(ap0, b1.x, acc[0][2]); acc[0][3] = ff2(ap0, b1.y, acc[0][3]);
        acc[1][0] = ff2(ap1, b0.x, acc[1][0]); acc[1][1] = ff2(ap1, b0.y, acc[1][1]);
        acc[1][2] = ff2(ap1, b1.x, acc[1][2]); acc[1][3] = ff2(ap1, b1.y, acc[1][3]);
    }
#pragma unroll
    for (int rr = 0; rr < 2; rr++) {
        int m = m0 + r0 + rr;
        if (m < NN) {
            float4 o0, o1;
            up2(acc[rr][0], o0.x, o0.y); up2(acc[rr][1], o0.z, o0.w);
            up2(acc[rr][2], o1.x, o1.y); up2(acc[rr][3], o1.z, o1.w);
            *(float4*)(P + (size_t)m * 64 + tx * 8) = o0;
            *(float4*)(P + (size_t)m * 64 + tx * 8 + 4) = o1;
        }
    }
}

// ---------------- fused layer: A=relu(bn((1+e)P+AGG)); H=relu(A@W2+b2);
//                  xs=H; Pn=H@W1n; zero AGG (for !LAST) ----------------------
template <int LAST>
__global__ __launch_bounds__(256) void layer_k(
    const float* __restrict__ P, float* __restrict__ AGG,
    const float* __restrict__ W2, const float* __restrict__ W1n,
    const float* __restrict__ b1, const float* __restrict__ gam,
    const float* __restrict__ bet, const float* __restrict__ mean,
    const float* __restrict__ var, const float* __restrict__ epsp,
    const float* __restrict__ b2, float* __restrict__ xs,
    float* __restrict__ Pn) {
    extern __shared__ float sm[];
    float* As  = sm;               // 64 x 68
    float* Hs  = As + 64 * 68;     // 64 x 68
    float* Bs  = Hs + 64 * 68;     // 64 x 64 (W2)
    float* Bs2 = Bs + 64 * 64;     // 64 x 64 (W1n)
    float* sc  = Bs2 + 64 * 64;
    float* sh  = sc + 64;
    int tid = threadIdx.x, m0 = blockIdx.x * 64;

    if (tid < 64) {
        float s = gam[tid] * rsqrtf(var[tid] + 1e-5f);
        sc[tid] = s;
        sh[tid] = (b1[tid] - mean[tid]) * s + bet[tid];
    }
    float ev = 1.0f + epsp[0];
    for (int i = tid; i < 64 * 16; i += 256)
        ((float4*)Bs)[i] = ((const float4*)W2)[i];
    if constexpr (!LAST)
        for (int i = tid; i < 64 * 16; i += 256)
            ((float4*)Bs2)[i] = ((const float4*)W1n)[i];
    __syncthreads();

    // pointwise stage into As; zero AGG in-place (same thread read->write)
    for (int i = tid; i < 64 * 16; i += 256) {
        int r = i >> 4, ch = (i & 15) * 4, m = m0 + r;
        float4 o = make_float4(0.f, 0.f, 0.f, 0.f);
        if (m < NN) {
            float4 p = *(const float4*)(P + (size_t)m * 64 + ch);
            float4 a = *(const float4*)(AGG + (size_t)m * 64 + ch);
            o.x = fmaxf(fmaf(fmaf(ev, p.x, a.x), sc[ch + 0], sh[ch + 0]), 0.f);
            o.y = fmaxf(fmaf(fmaf(ev, p.y, a.y), sc[ch + 1], sh[ch + 1]), 0.f);
            o.z = fmaxf(fmaf(fmaf(ev, p.z, a.z), sc[ch + 2], sh[ch + 2]), 0.f);
            o.w = fmaxf(fmaf(fmaf(ev, p.w, a.w), sc[ch + 3], sh[ch + 3]), 0.f);
            if constexpr (!LAST)
                *(float4*)(AGG + (size_t)m * 64 + ch) = make_float4(0.f, 0.f, 0.f, 0.f);
        }
        *(float4*)(As + r * 68 + ch) = o;
    }
    __syncthreads();

    int tx = tid & 7, ty = tid >> 3, r0 = ty * 2;
    const u64* B8 = (const u64*)Bs;
    u64 acc[2][4] = {};
#pragma unroll 4
    for (int k = 0; k < 64; k++) {
        float a0 = As[r0 * 68 + k], a1 = As[r0 * 68 + 68 + k];
        u64 ap0 = pk2(a0, a0), ap1 = pk2(a1, a1);
        ulonglong2 b0 = *(const ulonglong2*)(B8 + k * 32 + tx * 4);
        ulonglong2 b1 = *(const ulonglong2*)(B8 + k * 32 + tx * 4 + 2);
        acc[0][0] = ff2(ap0, b0.x, acc[0][0]); acc[0][1] = ff2(ap0, b0.y, acc[0][1]);
        acc[0][2] = ff2(ap0, b1.x, acc[0][2]); acc[0][3] = ff2(ap0, b1.y, acc[0][3]);
        acc[1][0] = ff2(ap1, b0.x, acc[1][0]); acc[1][1] = ff2(ap1, b0.y, acc[1][1]);
        acc[1][2] = ff2(ap1, b1.x, acc[1][2]); acc[1][3] = ff2(ap1, b1.y, acc[1][3]);
    }
    // H = relu(acc + b2); write Hs (for GEMM2) and xs (global)
#pragma unroll
    for (int rr = 0; rr < 2; rr++) {
        float v[8];
        up2(acc[rr][0], v[0], v[1]); up2(acc[rr][1], v[2], v[3]);
        up2(acc[rr][2], v[4], v[5]); up2(acc[rr][3], v[6], v[7]);
#pragma unroll
        for (int j = 0; j < 8; j++) v[j] = fmaxf(v[j] + b2[tx * 8 + j], 0.f);
        float4 o0 = make_float4(v[0], v[1], v[2], v[3]);
        float4 o1 = make_float4(v[4], v[5], v[6], v[7]);
        if constexpr (!LAST) {
            *(float4*)(Hs + (r0 + rr) * 68 + tx * 8) = o0;
            *(float4*)(Hs + (r0 + rr) * 68 + tx * 8 + 4) = o1;
        }
        int m = m0 + r0 + rr;
        if (m < NN) {
            *(float4*)(xs + (size_t)m * 64 + tx * 8) = o0;
            *(float4*)(xs + (size_t)m * 64 + tx * 8 + 4) = o1;
        }
    }

    if constexpr (!LAST) {
        __syncthreads();
        const u64* C8 = (const u64*)Bs2;
        u64 acc2[2][4] = {};
#pragma unroll 4
        for (int k = 0; k < 64; k++) {
            float a0 = Hs[r0 * 68 + k], a1 = Hs[r0 * 68 + 68 + k];
            u64 ap0 = pk2(a0, a0), ap1 = pk2(a1, a1);
            ulonglong2 b0 = *(const ulonglong2*)(C8 + k * 32 + tx * 4);
            ulonglong2 b1 = *(const ulonglong2*)(C8 + k * 32 + tx * 4 + 2);
            acc2[0][0] = ff2(ap0, b0.x, acc2[0][0]); acc2[0][1] = ff2(ap0, b0.y, acc2[0][1]);
            acc2[0][2] = ff2(ap0, b1.x, acc2[0][2]); acc2[0][3] = ff2(ap0, b1.y, acc2[0][3]);
            acc2[1][0] = ff2(ap1, b0.x, acc2[1][0]); acc2[1][1] = ff2(ap1, b0.y, acc2[1][1]);
            acc2[1][2] = ff2(ap1, b1.x, acc2[1][2]); acc2[1][3] = ff2(ap1, b1.y, acc2[1][3]);
        }
#pragma unroll
        for (int rr = 0; rr < 2; rr++) {
            int m = m0 + r0 + rr;
            if (m < NN) {
                float4 o0, o1;
                up2(acc2[rr][0], o0.x, o0.y); up2(acc2[rr][1], o0.z, o0.w);
                up2(acc2[rr][2], o1.x, o1.y); up2(acc2[rr][3], o1.z, o1.w);
                *(float4*)(Pn + (size_t)m * 64 + tx * 8) = o0;
                *(float4*)(Pn + (size_t)m * 64 + tx * 8 + 4) = o1;
            }
        }
    }
}

// ---------------- final: out = concat(xs0,xs1,xs2) @ l2W + l2b --------------
__global__ __launch_bounds__(256) void final_k(const float* __restrict__ x0,
                                               const float* __restrict__ x1,
                                               const float* __restrict__ x2,
                                               const float* __restrict__ W,
                                               const float* __restrict__ bias,
                                               float* __restrict__ Out) {
    extern __shared__ float sm[];
    float* As = sm;              // 64 x 196
    float* Bs = As + 64 * 196;   // 192 x 32
    int tid = threadIdx.x, m0 = blockIdx.x * 64;

    for (int i = tid; i < 64 * 48; i += 256) {
        int r = i / 48, ch = (i % 48) * 4, m = m0 + r;
        float4 v = make_float4(0.f, 0.f, 0.f, 0.f);
        if (m < NN) {
            const float* src = ch < 64 ? x0 : (ch < 128 ? x1 : x2);
            v = *(const float4*)(src + (size_t)m * 64 + (ch & 63));
        }
        *(float4*)(As + r * 196 + ch) = v;
    }
    for (int i = tid; i < 192 * 8; i += 256)
        ((float4*)Bs)[i] = ((const float4*)W)[i];
    __syncthreads();

    int tx = tid & 7, ty = tid >> 3, r0 = ty * 2;
    const u64* B8 = (const u64*)Bs;
    u64 acc[2][2] = {};
#pragma unroll 4
    for (int k = 0; k < 192; k++) {
        float a0 = As[r0 * 196 + k], a1 = As[r0 * 196 + 196 + k];
        u64 ap0 = pk2(a0, a0), ap1 = pk2(a1, a1);
        ulonglong2 bb = *(const ulonglong2*)(B8 + k * 16 + tx * 2);
        acc[0][0] = ff2(ap0, bb.x, acc[0][0]); acc[0][1] = ff2(ap0, bb.y, acc[0][1]);
        acc[1][0] = ff2(ap1, bb.x, acc[1][0]); acc[1][1] = ff2(ap1, bb.y, acc[1][1]);
    }
#pragma unroll
    for (int rr = 0; rr < 2; rr++) {
        int m = m0 + r0 + rr;
        if (m < NN) {
            float4 o;
            up2(acc[rr][0], o.x, o.y); up2(acc[rr][1], o.z, o.w);
            o.x += bias[tx * 4 + 0]; o.y += bias[tx * 4 + 1];
            o.z += bias[tx * 4 + 2]; o.w += bias[tx * 4 + 3];
            *(float4*)(Out + (size_t)m * 32 + tx * 4) = o;
        }
    }
}

// ---------------- host launcher ---------------------------------------------
extern "C" void kernel_launch(void* const* d_in, const int* in_sizes, int n_in,
                              void* d_out, int out_size) {
    const float* x    = (const float*)d_in[0];
    const int*   ei   = (const int*)d_in[1];
    const float* ew   = (const float*)d_in[2];
    const float* eps  = (const float*)d_in[3];
    const float* W1_0 = (const float*)d_in[4];
    const float* b1_0 = (const float*)d_in[5];
    const float* W1_r = (const float*)d_in[6];
    const float* b1_r = (const float*)d_in[7];
    const float* W2   = (const float*)d_in[8];
    const float* b2   = (const float*)d_in[9];
    const float* gam  = (const float*)d_in[10];
    const float* bet  = (const float*)d_in[11];
    const float* mean = (const float*)d_in[12];
    const float* var  = (const float*)d_in[13];
    const float* l2W  = (const float*)d_in[14];
    const float* l2b  = (const float*)d_in[15];
    float* out = (float*)d_out;

    float *P0, *P1, *AGG, *XS;
    cudaGetSymbolAddress((void**)&P0, g_P0);
    cudaGetSymbolAddress((void**)&P1, g_P1);
    cudaGetSymbolAddress((void**)&AGG, g_agg);
    cudaGetSymbolAddress((void**)&XS, g_xs);
    float* xs0 = XS;
    float* xs1 = XS + (size_t)NN * 64;
    float* xs2 = XS + 2 * (size_t)NN * 64;

    const int SM_IN    = (64 * 132 + 128 * 64) * 4;                      // 66560
    const int SM_LAYER = (64 * 68 * 2 + 64 * 64 * 2 + 128) * 4;          // 68096
    const int SM_FIN   = (64 * 196 + 192 * 32) * 4;                      // 74752

    cudaFuncSetAttribute(input_k, cudaFuncAttributeMaxDynamicSharedMemorySize, SM_IN);
    cudaFuncSetAttribute(layer_k<0>, cudaFuncAttributeMaxDynamicSharedMemorySize, SM_LAYER);
    cudaFuncSetAttribute(layer_k<1>, cudaFuncAttributeMaxDynamicSharedMemorySize, SM_LAYER);
    cudaFuncSetAttribute(final_k, cudaFuncAttributeMaxDynamicSharedMemorySize, SM_FIN);

    const int GB = (NN + 63) / 64;       // 1563
    const int EB = (NE * 8) / 256;       // 31250

    detect_k<<<1, 1>>>(ei);

    // layer 0
    input_k<<<GB, 256, SM_IN>>>(x, W1_0, P0, AGG);
    edge_k<<<EB, 256>>>(ei, ew, P0, AGG);
    layer_k<0><<<GB, 256, SM_LAYER>>>(P0, AGG, W2, W1_r,
                                      b1_0, gam, bet, mean, var,
                                      eps, b2, xs0, P1);
    // layer 1
    edge_k<<<EB, 256>>>(ei, ew, P1, AGG);
    layer_k<0><<<GB, 256, SM_LAYER>>>(P1, AGG, W2 + 4096, W1_r + 4096,
                                      b1_r, gam + 64, bet + 64,
                                      mean + 64, var + 64,
                                      eps + 1, b2 + 64, xs1, P0);
    // layer 2
    edge_k<<<EB, 256>>>(ei, ew, P0, AGG);
    layer_k<1><<<GB, 256, SM_LAYER>>>(P0, AGG, W2 + 8192, nullptr,
                                      b1_r + 64, gam + 128, bet + 128,
                                      mean + 128, var + 128,
                                      eps + 2, b2 + 128, xs2, nullptr);
    // final projection
    final_k<<<GB, 256, SM_FIN>>>(xs0, xs1, xs2, l2W, l2b, out);
}

// round 5
// speedup vs baseline: 1.5551x; 1.5551x over previous
#include <cuda_runtime.h>
#include <cstdint>

#define NN 100000
#define NE 1000000
#define HID 64

typedef unsigned long long u64;

// ---------------- device scratch ----------------
__device__ float g_P[(size_t)NN * HID];
__device__ float g_agg[(size_t)NN * HID];
__device__ float g_xs[3][(size_t)NN * HID];
__device__ int   g_is64;

// ---------------- f32x2 packed helpers --------------------------------------
__device__ __forceinline__ u64 pk2(float x, float y) {
    u64 r; asm("mov.b64 %0,{%1,%2};" : "=l"(r) : "f"(x), "f"(y)); return r;
}
__device__ __forceinline__ void up2(u64 v, float& x, float& y) {
    asm("mov.b64 {%0,%1},%2;" : "=f"(x), "=f"(y) : "l"(v));
}
__device__ __forceinline__ u64 ff2(u64 a, u64 b, u64 c) {
    u64 d; asm("fma.rn.f32x2 %0,%1,%2,%3;" : "=l"(d) : "l"(a), "l"(b), "l"(c));
    return d;
}

// ---------------- dtype detection (int64 vs int32 edge_index) ---------------
__global__ void detect_k(const int* __restrict__ ei) {
    if (threadIdx.x == 0 && blockIdx.x == 0) {
        int is64 = 1;
        for (int e = 0; e < 64; e++)
            if (ei[2 * e + 1] != 0) { is64 = 0; break; }
        g_is64 = is64;
    }
}

// ---------------- edge scatter-add: agg[dst] += w * P[src] ------------------
// 8 threads per edge, 8 channels each
__global__ __launch_bounds__(256) void edge_k(const int* __restrict__ ei,
                                              const float* __restrict__ ew,
                                              const float* __restrict__ P,
                                              float* __restrict__ agg) {
    int t = blockIdx.x * 256 + threadIdx.x;
    int e = t >> 3;
    int g = (t & 7) * 8;
    int src, dst;
    if (g_is64) {
        const long long* e64 = (const long long*)ei;
        src = (int)e64[e];
        dst = (int)e64[NE + e];
    } else {
        src = ei[e];
        dst = ei[NE + e];
    }
    float w = ew[e];
    const float4* vp = (const float4*)(P + (size_t)src * HID + g);
    float4 v0 = vp[0], v1 = vp[1];
    float* p = agg + (size_t)dst * HID + g;
    asm volatile("red.global.add.v4.f32 [%0],{%1,%2,%3,%4};"
                 :: "l"(p), "f"(v0.x * w), "f"(v0.y * w), "f"(v0.z * w), "f"(v0.w * w)
                 : "memory");
    asm volatile("red.global.add.v4.f32 [%0],{%1,%2,%3,%4};"
                 :: "l"(p + 4), "f"(v1.x * w), "f"(v1.y * w), "f"(v1.z * w), "f"(v1.w * w)
                 : "memory");
}

// ---------------- fused GEMM kernel (R2 structure + FFMA2 inner loop) -------
// MODE 0: Out = A0 @ B                  (projection; ZERO -> also zero AGGz)
// MODE 1: A = relu(bn((1+eps)*A0 + A1 + b1)); Out = relu(A@B + b2)
// MODE 2: A = concat(A0,A1,A2); Out = A@B + bias2
template <int K, int NOUT, int MODE, int ZERO>
__global__ __launch_bounds__(256) void gemm_k(
    const float* __restrict__ A0, const float* __restrict__ A1,
    const float* __restrict__ A2, const float* __restrict__ B,
    const float* __restrict__ b1, const float* __restrict__ gam,
    const float* __restrict__ bet, const float* __restrict__ mean,
    const float* __restrict__ var, const float* __restrict__ epsp,
    const float* __restrict__ bias2, float* __restrict__ Out,
    float* __restrict__ AGGz) {
    constexpr int BM = 64;
    constexpr int KP = K + 1;             // pad to kill LDS bank conflicts
    constexpr int CG = NOUT / 4;          // column groups (4 cols / thread)
    constexpr int RPT = (BM * CG) / 256;  // rows per thread

    extern __shared__ float sm[];
    float* As = sm;                  // BM * KP
    float* Bs = As + BM * KP;        // K * NOUT  (16B-aligned: BM*KP*4 % 16 == 0)
    float* sc = Bs + K * NOUT;       // 64 (MODE 1)
    float* sh = sc + 64;             // 64 (MODE 1)

    int tid = threadIdx.x;
    int m0 = blockIdx.x * BM;

    if constexpr (MODE == 1) {
        if (tid < 64) {
            float s = gam[tid] * rsqrtf(var[tid] + 1e-5f);
            sc[tid] = s;
            sh[tid] = (b1[tid] - mean[tid]) * s + bet[tid];
        }
        __syncthreads();
    }

    float ev = 0.f;
    if constexpr (MODE == 1) ev = 1.0f + epsp[0];

    // ---- stage A tile (fused pointwise for MODE 1/2) ----
    for (int i = tid; i < BM * (K / 4); i += 256) {
        int r = i / (K / 4), c4 = i % (K / 4);
        int m = m0 + r;
        float o0 = 0.f, o1 = 0.f, o2 = 0.f, o3 = 0.f;
        if (m < NN) {
            if constexpr (MODE == 0) {
                float4 v = *(const float4*)(A0 + (size_t)m * K + c4 * 4);
                o0 = v.x; o1 = v.y; o2 = v.z; o3 = v.w;
            } else if constexpr (MODE == 1) {
                float4 p = *(const float4*)(A0 + (size_t)m * HID + c4 * 4);
                float4 a = *(const float4*)(A1 + (size_t)m * HID + c4 * 4);
                int ch = c4 * 4;
                o0 = fmaxf(fmaf(fmaf(ev, p.x, a.x), sc[ch + 0], sh[ch + 0]), 0.f);
                o1 = fmaxf(fmaf(fmaf(ev, p.y, a.y), sc[ch + 1], sh[ch + 1]), 0.f);
                o2 = fmaxf(fmaf(fmaf(ev, p.z, a.z), sc[ch + 2], sh[ch + 2]), 0.f);
                o3 = fmaxf(fmaf(fmaf(ev, p.w, a.w), sc[ch + 3], sh[ch + 3]), 0.f);
            } else {
                int ch = c4 * 4;
                const float* src = (ch < 64) ? A0 : (ch < 128 ? A1 : A2);
                int cc = ch & 63;
                float4 v = *(const float4*)(src + (size_t)m * HID + cc);
                o0 = v.x; o1 = v.y; o2 = v.z; o3 = v.w;
            }
        }
        float* dst = As + r * KP + c4 * 4;
        dst[0] = o0; dst[1] = o1; dst[2] = o2; dst[3] = o3;
    }
    // ---- zero next AGG tile (projection kernels only) ----
    if constexpr (ZERO) {
        for (int i = tid; i < 64 * 16; i += 256) {
            int r = i >> 4, m = m0 + r;
            if (m < NN)
                *(float4*)(AGGz + (size_t)m * 64 + (i & 15) * 4) =
                    make_float4(0.f, 0.f, 0.f, 0.f);
        }
    }
    // ---- stage B tile ----
    for (int i = tid; i < K * NOUT / 4; i += 256)
        ((float4*)Bs)[i] = ((const float4*)B)[i];
    __syncthreads();

    int tx = tid % CG, ty = tid / CG;
    const ulonglong2* B16 = (const ulonglong2*)Bs;
    u64 acc[RPT][2] = {};

#pragma unroll 8
    for (int k = 0; k < K; k++) {
        ulonglong2 b = B16[k * CG + tx];
#pragma unroll
        for (int i = 0; i < RPT; i++) {
            float a = As[(ty * RPT + i) * KP + k];
            u64 ap = pk2(a, a);
            acc[i][0] = ff2(ap, b.x, acc[i][0]);
            acc[i][1] = ff2(ap, b.y, acc[i][1]);
        }
    }

    float4 bb = make_float4(0.f, 0.f, 0.f, 0.f);
    if constexpr (MODE != 0) bb = *(const float4*)(bias2 + tx * 4);

#pragma unroll
    for (int i = 0; i < RPT; i++) {
        int m = m0 + ty * RPT + i;
        if (m < NN) {
            float4 o;
            up2(acc[i][0], o.x, o.y);
            up2(acc[i][1], o.z, o.w);
            o.x += bb.x; o.y += bb.y; o.z += bb.z; o.w += bb.w;
            if constexpr (MODE == 1) {
                o.x = fmaxf(o.x, 0.f); o.y = fmaxf(o.y, 0.f);
                o.z = fmaxf(o.z, 0.f); o.w = fmaxf(o.w, 0.f);
            }
            *(float4*)(Out + (size_t)m * NOUT + tx * 4) = o;
        }
    }
}

// ---------------- host launcher ---------------------------------------------
extern "C" void kernel_launch(void* const* d_in, const int* in_sizes, int n_in,
                              void* d_out, int out_size) {
    const float* x    = (const float*)d_in[0];
    const int*   ei   = (const int*)d_in[1];
    const float* ew   = (const float*)d_in[2];
    const float* eps  = (const float*)d_in[3];
    const float* W1_0 = (const float*)d_in[4];
    const float* b1_0 = (const float*)d_in[5];
    const float* W1_r = (const float*)d_in[6];
    const float* b1_r = (const float*)d_in[7];
    const float* W2   = (const float*)d_in[8];
    const float* b2   = (const float*)d_in[9];
    const float* gam  = (const float*)d_in[10];
    const float* bet  = (const float*)d_in[11];
    const float* mean = (const float*)d_in[12];
    const float* var  = (const float*)d_in[13];
    const float* l2W  = (const float*)d_in[14];
    const float* l2b  = (const float*)d_in[15];
    float* out = (float*)d_out;

    float *P, *AGG, *XS;
    cudaGetSymbolAddress((void**)&P, g_P);
    cudaGetSymbolAddress((void**)&AGG, g_agg);
    cudaGetSymbolAddress((void**)&XS, g_xs);
    float* xs0 = XS;
    float* xs1 = XS + (size_t)NN * HID;
    float* xs2 = XS + 2 * (size_t)NN * HID;

    const int SM_128_64 = (64 * 129 + 128 * 64 + 128) * 4;  // 66304
    const int SM_64_64  = (64 * 65 + 64 * 64 + 128) * 4;    // 33536
    const int SM_192_32 = (64 * 193 + 192 * 32 + 128) * 4;  // 74496

    cudaFuncSetAttribute(gemm_k<128, 64, 0, 1>,
                         cudaFuncAttributeMaxDynamicSharedMemorySize, SM_128_64);
    cudaFuncSetAttribute(gemm_k<192, 32, 2, 0>,
                         cudaFuncAttributeMaxDynamicSharedMemorySize, SM_192_32);

    const int GB = (NN + 63) / 64;   // 1563
    const int EB = (NE * 8) / 256;   // 31250

    detect_k<<<1, 1>>>(ei);

    // ----- layer 0 -----
    gemm_k<128, 64, 0, 1><<<GB, 256, SM_128_64>>>(x, 0, 0, W1_0,
                                                  0, 0, 0, 0, 0, 0, 0, P, AGG);
    edge_k<<<EB, 256>>>(ei, ew, P, AGG);
    gemm_k<64, 64, 1, 0><<<GB, 256, SM_64_64>>>(P, AGG, 0, W2,
                                                b1_0, gam, bet, mean, var,
                                                eps, b2, xs0, 0);
    // ----- layer 1 -----
    gemm_k<64, 64, 0, 1><<<GB, 256, SM_64_64>>>(xs0, 0, 0, W1_r,
                                                0, 0, 0, 0, 0, 0, 0, P, AGG);
    edge_k<<<EB, 256>>>(ei, ew, P, AGG);
    gemm_k<64, 64, 1, 0><<<GB, 256, SM_64_64>>>(P, AGG, 0, W2 + 4096,
                                                b1_r, gam + 64, bet + 64,
                                                mean + 64, var + 64,
                                                eps + 1, b2 + 64, xs1, 0);
    // ----- layer 2 -----
    gemm_k<64, 64, 0, 1><<<GB, 256, SM_64_64>>>(xs1, 0, 0, W1_r + 4096,
                                                0, 0, 0, 0, 0, 0, 0, P, AGG);
    edge_k<<<EB, 256>>>(ei, ew, P, AGG);
    gemm_k<64, 64, 1, 0><<<GB, 256, SM_64_64>>>(P, AGG, 0, W2 + 8192,
                                                b1_r + 64, gam + 128, bet + 128,
                                                mean + 128, var + 128,
                                                eps + 2, b2 + 128, xs2, 0);
    // ----- final projection (concat fused) -----
    gemm_k<192, 32, 2, 0><<<GB, 256, SM_192_32>>>(xs0, xs1, xs2, l2W,
                                                  0, 0, 0, 0, 0, 0, l2b, out, 0);
}

// round 7
// speedup vs baseline: 1.7706x; 1.1386x over previous
#include <cuda_runtime.h>
#include <cstdint>

#define NN 100000
#define NE 1000000
#define HID 64

typedef unsigned long long u64;

// ---------------- device scratch ----------------
__device__ float g_P[(size_t)NN * HID];
__device__ float g_agg[(size_t)NN * HID];
__device__ float g_xs[3][(size_t)NN * HID];
__device__ int   g_is64;

// ---------------- f32x2 packed helpers --------------------------------------
__device__ __forceinline__ u64 pk2(float x, float y) {
    u64 r; asm("mov.b64 %0,{%1,%2};" : "=l"(r) : "f"(x), "f"(y)); return r;
}
__device__ __forceinline__ void up2(u64 v, float& x, float& y) {
    asm("mov.b64 {%0,%1},%2;" : "=f"(x), "=f"(y) : "l"(v));
}
__device__ __forceinline__ u64 ff2(u64 a, u64 b, u64 c) {
    u64 d; asm("fma.rn.f32x2 %0,%1,%2,%3;" : "=l"(d) : "l"(a), "l"(b), "l"(c));
    return d;
}

// ---------------- dtype detection (int64 vs int32 edge_index) ---------------
__global__ void detect_k(const int* __restrict__ ei) {
    if (threadIdx.x == 0 && blockIdx.x == 0) {
        int is64 = 1;
        for (int e = 0; e < 64; e++)
            if (ei[2 * e + 1] != 0) { is64 = 0; break; }
        g_is64 = is64;
    }
}

// ---------------- edge scatter-add: agg[dst] += w * P[src] ------------------
// 16 threads per edge, 4 channels each (proven R2 form: 65.7us)
__global__ __launch_bounds__(256) void edge_k(const int* __restrict__ ei,
                                              const float* __restrict__ ew,
                                              const float* __restrict__ P,
                                              float* __restrict__ agg) {
    int t = blockIdx.x * 256 + threadIdx.x;
    int e = t >> 4;
    int g = (t & 15) * 4;
    int src, dst;
    if (g_is64) {
        const long long* e64 = (const long long*)ei;
        src = (int)e64[e];
        dst = (int)e64[NE + e];
    } else {
        src = ei[e];
        dst = ei[NE + e];
    }
    float w = ew[e];
    float4 v = *(const float4*)(P + (size_t)src * HID + g);
    float* p = agg + (size_t)dst * HID + g;
    asm volatile("red.global.add.v4.f32 [%0],{%1,%2,%3,%4};"
                 :: "l"(p), "f"(v.x * w), "f"(v.y * w), "f"(v.z * w), "f"(v.w * w)
                 : "memory");
}

// ---------------- fused GEMM kernel -----------------------------------------
// MODE 0: Out = A0 @ B                  (projection; ZERO -> also zero AGGz)
// MODE 1: A = relu(bn((1+eps)*A0 + A1 + b1)); Out = relu(A@B + b2)
// MODE 2: A = concat(A0,A1,A2); Out = A@B + bias2
template <int K, int NOUT, int MODE, int ZERO>
__global__ __launch_bounds__(256) void gemm_k(
    const float* __restrict__ A0, const float* __restrict__ A1,
    const float* __restrict__ A2, const float* __restrict__ B,
    const float* __restrict__ b1, const float* __restrict__ gam,
    const float* __restrict__ bet, const float* __restrict__ mean,
    const float* __restrict__ var, const float* __restrict__ epsp,
    const float* __restrict__ bias2, float* __restrict__ Out,
    float* __restrict__ AGGz) {
    constexpr int BM = 64;
    constexpr int KP = K + 4;             // pad: float4-aligned rows, no mainloop conflicts
    constexpr int CG = NOUT / 4;          // column groups (4 cols / thread)
    constexpr int RPT = (BM * CG) / 256;  // rows per thread

    extern __shared__ float sm[];
    float* As = sm;                  // BM * KP
    float* Bs = As + BM * KP;        // K * NOUT
    float* sc = Bs + K * NOUT;       // 64 (MODE 1)
    float* sh = sc + 64;             // 64 (MODE 1)

    int tid = threadIdx.x;
    int m0 = blockIdx.x * BM;

    if constexpr (MODE == 1) {
        if (tid < 64) {
            float s = gam[tid] * rsqrtf(var[tid] + 1e-5f);
            sc[tid] = s;
            sh[tid] = (b1[tid] - mean[tid]) * s + bet[tid];
        }
        __syncthreads();
    }

    float ev = 0.f;
    if constexpr (MODE == 1) ev = 1.0f + epsp[0];

    // ---- stage A tile (fused pointwise for MODE 1/2) ----
    for (int i = tid; i < BM * (K / 4); i += 256) {
        int r = i / (K / 4), c4 = i % (K / 4);
        int m = m0 + r;
        float o0 = 0.f, o1 = 0.f, o2 = 0.f, o3 = 0.f;
        if (m < NN) {
            if constexpr (MODE == 0) {
                float4 v = *(const float4*)(A0 + (size_t)m * K + c4 * 4);
                o0 = v.x; o1 = v.y; o2 = v.z; o3 = v.w;
            } else if constexpr (MODE == 1) {
                float4 p = *(const float4*)(A0 + (size_t)m * HID + c4 * 4);
                float4 a = *(const float4*)(A1 + (size_t)m * HID + c4 * 4);
                int ch = c4 * 4;
                o0 = fmaxf(fmaf(fmaf(ev, p.x, a.x), sc[ch + 0], sh[ch + 0]), 0.f);
                o1 = fmaxf(fmaf(fmaf(ev, p.y, a.y), sc[ch + 1], sh[ch + 1]), 0.f);
                o2 = fmaxf(fmaf(fmaf(ev, p.z, a.z), sc[ch + 2], sh[ch + 2]), 0.f);
                o3 = fmaxf(fmaf(fmaf(ev, p.w, a.w), sc[ch + 3], sh[ch + 3]), 0.f);
            } else {
                int ch = c4 * 4;
                const float* src = (ch < 64) ? A0 : (ch < 128 ? A1 : A2);
                int cc = ch & 63;
                float4 v = *(const float4*)(src + (size_t)m * HID + cc);
                o0 = v.x; o1 = v.y; o2 = v.z; o3 = v.w;
            }
        }
        float* dst = As + r * KP + c4 * 4;
        dst[0] = o0; dst[1] = o1; dst[2] = o2; dst[3] = o3;
    }
    // ---- zero next AGG tile (projection kernels only) ----
    if constexpr (ZERO) {
        for (int i = tid; i < 64 * 16; i += 256) {
            int r = i >> 4, m = m0 + r;
            if (m < NN)
                *(float4*)(AGGz + (size_t)m * 64 + (i & 15) * 4) =
                    make_float4(0.f, 0.f, 0.f, 0.f);
        }
    }
    // ---- stage B tile ----
    for (int i = tid; i < K * NOUT / 4; i += 256)
        ((float4*)Bs)[i] = ((const float4*)B)[i];
    __syncthreads();

    // ---- mainloop: k in pairs; A via LDS.64, B float4 = 2 packed col-pairs -
    int tx = tid % CG, ty = tid / CG;
    u64 acc[RPT][2] = {};

#pragma unroll 4
    for (int k = 0; k < K; k += 2) {
        ulonglong2 b0 = *(const ulonglong2*)(Bs + k * NOUT + tx * 4);
        ulonglong2 b1 = *(const ulonglong2*)(Bs + (k + 1) * NOUT + tx * 4);
        float2 a[RPT];
#pragma unroll
        for (int i = 0; i < RPT; i++)
            a[i] = *(const float2*)(As + (ty * RPT + i) * KP + k);
#pragma unroll
        for (int i = 0; i < RPT; i++) {
            u64 ap0 = pk2(a[i].x, a[i].x);
            acc[i][0] = ff2(ap0, b0.x, acc[i][0]);
            acc[i][1] = ff2(ap0, b0.y, acc[i][1]);
            u64 ap1 = pk2(a[i].y, a[i].y);
            acc[i][0] = ff2(ap1, b1.x, acc[i][0]);
            acc[i][1] = ff2(ap1, b1.y, acc[i][1]);
        }
    }

    float4 bb = make_float4(0.f, 0.f, 0.f, 0.f);
    if constexpr (MODE != 0) bb = *(const float4*)(bias2 + tx * 4);

#pragma unroll
    for (int i = 0; i < RPT; i++) {
        int m = m0 + ty * RPT + i;
        if (m < NN) {
            float4 o;
            up2(acc[i][0], o.x, o.y);
            up2(acc[i][1], o.z, o.w);
            o.x += bb.x; o.y += bb.y; o.z += bb.z; o.w += bb.w;
            if constexpr (MODE == 1) {
                o.x = fmaxf(o.x, 0.f); o.y = fmaxf(o.y, 0.f);
                o.z = fmaxf(o.z, 0.f); o.w = fmaxf(o.w, 0.f);
            }
            *(float4*)(Out + (size_t)m * NOUT + tx * 4) = o;
        }
    }
}

// ---------------- host launcher ---------------------------------------------
extern "C" void kernel_launch(void* const* d_in, const int* in_sizes, int n_in,
                              void* d_out, int out_size) {
    const float* x    = (const float*)d_in[0];
    const int*   ei   = (const int*)d_in[1];
    const float* ew   = (const float*)d_in[2];
    const float* eps  = (const float*)d_in[3];
    const float* W1_0 = (const float*)d_in[4];
    const float* b1_0 = (const float*)d_in[5];
    const float* W1_r = (const float*)d_in[6];
    const float* b1_r = (const float*)d_in[7];
    const float* W2   = (const float*)d_in[8];
    const float* b2   = (const float*)d_in[9];
    const float* gam  = (const float*)d_in[10];
    const float* bet  = (const float*)d_in[11];
    const float* mean = (const float*)d_in[12];
    const float* var  = (const float*)d_in[13];
    const float* l2W  = (const float*)d_in[14];
    const float* l2b  = (const float*)d_in[15];
    float* out = (float*)d_out;

    float *P, *AGG, *XS;
    cudaGetSymbolAddress((void**)&P, g_P);
    cudaGetSymbolAddress((void**)&AGG, g_agg);
    cudaGetSymbolAddress((void**)&XS, g_xs);
    float* xs0 = XS;
    float* xs1 = XS + (size_t)NN * HID;
    float* xs2 = XS + 2 * (size_t)NN * HID;

    const int SM_128_64 = (64 * 132 + 128 * 64 + 128) * 4;  // 67072
    const int SM_64_64  = (64 * 68 + 64 * 64 + 128) * 4;    // 34304
    const int SM_192_32 = (64 * 196 + 192 * 32 + 128) * 4;  // 75264

    cudaFuncSetAttribute(gemm_k<128, 64, 0, 1>,
                         cudaFuncAttributeMaxDynamicSharedMemorySize, SM_128_64);
    cudaFuncSetAttribute(gemm_k<192, 32, 2, 0>,
                         cudaFuncAttributeMaxDynamicSharedMemorySize, SM_192_32);

    const int GB = (NN + 63) / 64;    // 1563
    const int EB = (NE * 16) / 256;   // 62500

    detect_k<<<1, 1>>>(ei);

    // ----- layer 0 -----
    gemm_k<128, 64, 0, 1><<<GB, 256, SM_128_64>>>(x, 0, 0, W1_0,
                                                  0, 0, 0, 0, 0, 0, 0, P, AGG);
    edge_k<<<EB, 256>>>(ei, ew, P, AGG);
    gemm_k<64, 64, 1, 0><<<GB, 256, SM_64_64>>>(P, AGG, 0, W2,
                                                b1_0, gam, bet, mean, var,
                                                eps, b2, xs0, 0);
    // ----- layer 1 -----
    gemm_k<64, 64, 0, 1><<<GB, 256, SM_64_64>>>(xs0, 0, 0, W1_r,
                                                0, 0, 0, 0, 0, 0, 0, P, AGG);
    edge_k<<<EB, 256>>>(ei, ew, P, AGG);
    gemm_k<64, 64, 1, 0><<<GB, 256, SM_64_64>>>(P, AGG, 0, W2 + 4096,
                                                b1_r, gam + 64, bet + 64,
                                                mean + 64, var + 64,
                                                eps + 1, b2 + 64, xs1, 0);
    // ----- layer 2 -----
    gemm_k<64, 64, 0, 1><<<GB, 256, SM_64_64>>>(xs1, 0, 0, W1_r + 4096,
                                                0, 0, 0, 0, 0, 0, 0, P, AGG);
    edge_k<<<EB, 256>>>(ei, ew, P, AGG);
    gemm_k<64, 64, 1, 0><<<GB, 256, SM_64_64>>>(P, AGG, 0, W2 + 8192,
                                                b1_r + 64, gam + 128, bet + 128,
                                                mean + 128, var + 128,
                                                eps + 2, b2 + 128, xs2, 0);
    // ----- final projection (concat fused) -----
    gemm_k<192, 32, 2, 0><<<GB, 256, SM_192_32>>>(xs0, xs1, xs2, l2W,
                                                  0, 0, 0, 0, 0, 0, l2b, out, 0);
}